// round 1
// baseline (speedup 1.0000x reference)
#include <cuda_runtime.h>
#include <cuda_bf16.h>
#include <cstdint>

// ---------------------------------------------------------------------------
// SocialPooling: pooled[i] = scatter-add of neighbor hidden states into an
// 8x8 grid around anchor i, then out = relu(pooled @ W + b).
// Shapes (fixed instance): S=64, P=64, B=4096, H=64, g2=64, feat=4096, N=1024.
// ---------------------------------------------------------------------------

#define H_DIM 64
#define G2    64
#define PP    64   // persons per sequence

// 64 MB scratch for the dense pooled matrix (B x g2*H = 4096 x 4096 fp32).
__device__ float g_pooled[4096u * 4096u];

// ---------------------------------------------------------------------------
// Kernel 1: pooling. One block per anchor (B blocks), 64 threads.
// Thread t owns hidden-dim t: accumulation loop over j has no write races.
// ---------------------------------------------------------------------------
__global__ __launch_bounds__(64) void pool_kernel(
    const float* __restrict__ h_states,   // (B, H)
    const float* __restrict__ end_pos,    // (B, 2)
    int P)
{
    int i = blockIdx.x;       // global anchor index
    int s = i / P;            // sequence
    int p = i % P;            // person within sequence
    int t = threadIdx.x;      // 0..63 = hidden dim lane

    __shared__ float  sh_hidden[PP * H_DIM];   // 16 KB
    __shared__ float2 sh_pos[PP];
    __shared__ int    sh_cell[PP];
    __shared__ float  sh_pool[G2 * H_DIM];     // 16 KB

    const float* hseq = h_states + (size_t)s * P * H_DIM;
    #pragma unroll
    for (int k = t; k < PP * H_DIM; k += 64) sh_hidden[k] = hseq[k];
    if (t < PP) sh_pos[t] = ((const float2*)end_pos)[(size_t)s * P + t];
    __syncthreads();

    float px = sh_pos[p].x, py = sh_pos[p].y;
    float tlx = px - 1.0f, tly = py + 1.0f;
    float brx = px + 1.0f, bry = py - 1.0f;

    if (t < PP) {
        float ox = sh_pos[t].x, oy = sh_pos[t].y;
        bool oob = (ox >= brx) || (ox <= tlx) || (oy >= tly) || (oy <= bry) || (t == p);
        // match JAX: floor((d)/NS*GRID); /2*8 are exact pow2 ops
        int cx = (int)floorf((ox - tlx) / 2.0f * 8.0f);
        int cy = (int)floorf((tly - oy) / 2.0f * 8.0f);
        int c = cx + cy * 8;
        sh_cell[t] = (oob || c < 0 || c >= G2) ? -1 : c;
    }
    #pragma unroll
    for (int k = t; k < G2 * H_DIM; k += 64) sh_pool[k] = 0.0f;
    __syncthreads();

    // scatter-accumulate: thread t handles dim t for every neighbor j
    for (int j = 0; j < PP; j++) {
        int c = sh_cell[j];
        if (c >= 0) sh_pool[c * H_DIM + t] += sh_hidden[j * H_DIM + t];
    }
    __syncthreads();

    // write full dense row (4096 floats) to global scratch
    float4*       dst = (float4*)(g_pooled + (size_t)i * (G2 * H_DIM));
    const float4* src = (const float4*)sh_pool;
    #pragma unroll
    for (int k = t; k < (G2 * H_DIM) / 4; k += 64) dst[k] = src[k];
}

// ---------------------------------------------------------------------------
// Kernel 2: C = relu(A @ B + bias). A = g_pooled (M x K), B = W (K x N).
// 128x128 block tile, BK=16, 256 threads, 8x8 register micro-tile.
// ---------------------------------------------------------------------------
__global__ __launch_bounds__(256) void gemm_bias_relu_kernel(
    const float* __restrict__ Bmat,    // W: (K, N) row-major
    const float* __restrict__ bias,    // (N)
    float* __restrict__ C,             // (M, N)
    int M, int N, int K)
{
    const int BM = 128, BN = 128, BK = 16, TM = 8, TN = 8;
    __shared__ float As[BK][BM];       // transposed A tile
    __shared__ float Bs[BK][BN];

    int bx = blockIdx.x;   // along N
    int by = blockIdx.y;   // along M
    int tid = threadIdx.x;
    int tx = tid % 16;     // 16 threads along N
    int ty = tid / 16;     // 16 threads along M

    float acc[TM][TN] = {};

    // A-tile load mapping: 128 rows x 16 cols = 128 x 4 float4; 2 per thread
    int arow = tid / 4;          // 0..63 (+64 second pass)
    int acol = tid % 4;          // float4 index along K
    // B-tile load mapping: 16 rows x 128 cols = 16 x 32 float4; 2 per thread
    int brow = tid / 32;         // 0..7 (+8 second pass)
    int bcol = tid % 32;

    const float* Ablk = g_pooled + (size_t)(by * BM) * K;
    const float* Bblk = Bmat + (size_t)(bx * BN);

    for (int k0 = 0; k0 < K; k0 += BK) {
        #pragma unroll
        for (int r = 0; r < 2; r++) {
            int row = arow + r * 64;
            float4 v = *(const float4*)(Ablk + (size_t)row * K + k0 + acol * 4);
            As[acol * 4 + 0][row] = v.x;
            As[acol * 4 + 1][row] = v.y;
            As[acol * 4 + 2][row] = v.z;
            As[acol * 4 + 3][row] = v.w;
        }
        #pragma unroll
        for (int r = 0; r < 2; r++) {
            int row = brow + r * 8;
            *(float4*)(&Bs[row][bcol * 4]) =
                *(const float4*)(Bblk + (size_t)(k0 + row) * N + bcol * 4);
        }
        __syncthreads();

        #pragma unroll
        for (int k = 0; k < BK; k++) {
            float a[TM], b[TN];
            #pragma unroll
            for (int m = 0; m < TM; m += 4) {
                float4 v = *(const float4*)(&As[k][ty * TM + m]);
                a[m] = v.x; a[m+1] = v.y; a[m+2] = v.z; a[m+3] = v.w;
            }
            #pragma unroll
            for (int n = 0; n < TN; n += 4) {
                float4 v = *(const float4*)(&Bs[k][tx * TN + n]);
                b[n] = v.x; b[n+1] = v.y; b[n+2] = v.z; b[n+3] = v.w;
            }
            #pragma unroll
            for (int m = 0; m < TM; m++)
                #pragma unroll
                for (int n = 0; n < TN; n++)
                    acc[m][n] = fmaf(a[m], b[n], acc[m][n]);
        }
        __syncthreads();
    }

    // epilogue: bias + relu, vectorized stores
    #pragma unroll
    for (int m = 0; m < TM; m++) {
        int gm = by * BM + ty * TM + m;
        #pragma unroll
        for (int n = 0; n < TN; n += 4) {
            int gn = bx * BN + tx * TN + n;
            float4 v;
            v.x = fmaxf(acc[m][n + 0] + bias[gn + 0], 0.0f);
            v.y = fmaxf(acc[m][n + 1] + bias[gn + 1], 0.0f);
            v.z = fmaxf(acc[m][n + 2] + bias[gn + 2], 0.0f);
            v.w = fmaxf(acc[m][n + 3] + bias[gn + 3], 0.0f);
            *(float4*)(C + (size_t)gm * N + gn) = v;
        }
    }
}

// ---------------------------------------------------------------------------
// Launch
// ---------------------------------------------------------------------------
extern "C" void kernel_launch(void* const* d_in, const int* in_sizes, int n_in,
                              void* d_out, int out_size)
{
    const float* h_states = (const float*)d_in[0];   // (1, B, 64)
    // d_in[1] = seq_start_end (unused by reference beyond shape)
    const float* end_pos  = (const float*)d_in[2];   // (B, 2)
    // d_in[3] = rel_pos (unused)
    const float* W        = (const float*)d_in[4];   // (feat, N)
    const float* bias     = (const float*)d_in[5];   // (N)
    float* out = (float*)d_out;

    int S = in_sizes[1] / 2;            // 64
    int B = in_sizes[2] / 2;            // 4096
    int P = B / S;                      // 64
    int N = in_sizes[5];                // 1024
    int K = in_sizes[4] / N;            // 4096 (= g2 * H)
    int M = B;

    pool_kernel<<<B, 64>>>(h_states, end_pos, P);

    dim3 grid(N / 128, M / 128);        // (8, 32)
    gemm_bias_relu_kernel<<<grid, 256>>>(W, bias, out, M, N, K);
}

// round 3
// speedup vs baseline: 3.1201x; 3.1201x over previous
#include <cuda_runtime.h>
#include <cuda_bf16.h>
#include <cstdint>

// ---------------------------------------------------------------------------
// SocialPooling: pooled[i] = scatter-add of neighbor hidden states into an
// 8x8 grid around anchor i, then out = relu(pooled @ W + b).
// Fixed instance: S=64, P=64, B=4096, H=64, g2=64 -> K=4096, N=1024.
// Round 3: mma.sync tf32 GEMM (base-ISA tensor path; tcgen05 is 'a'-gated
// and unavailable at the harness's compute_103 PTX target).
// ---------------------------------------------------------------------------

#define H_DIM 64
#define G2    64
#define PP    64

#define M_TOT 4096
#define N_TOT 1024
#define K_TOT 4096

#define BM 128
#define BN 128
#define BKK 32
#define NST 3
#define NC (K_TOT / BKK)        // 128 k-chunks

#define AS_STRIDE 36            // 32 + 4 pad  -> bank = 4*row + k  (conflict-free)
#define BS_STRIDE 136           // 128 + 8 pad -> bank = 8*k + n    (conflict-free)
#define STAGE_FLOATS (BM * AS_STRIDE + BKK * BS_STRIDE)   // 9216 + 4352 = 13568
#define SMEM_BYTES (NST * STAGE_FLOATS * 4)               // 162816... check: 13568*4*3 = 162816

// scratch: dense tf32-rounded pooled A (64 MB) + tf32-rounded W (16 MB)
__device__ float g_pooled[(size_t)M_TOT * K_TOT];
__device__ float g_Wr[(size_t)K_TOT * N_TOT];

// ---------------------------------------------------------------------------
// helpers
// ---------------------------------------------------------------------------
__device__ __forceinline__ float to_tf32(float x) {
    uint32_t r;
    asm("cvt.rna.tf32.f32 %0, %1;" : "=r"(r) : "f"(x));
    return __uint_as_float(r);
}
__device__ __forceinline__ uint32_t smem_u32(const void* p) {
    uint32_t a;
    asm("{ .reg .u64 t; cvta.to.shared.u64 t, %1; cvt.u32.u64 %0, t; }" : "=r"(a) : "l"(p));
    return a;
}
__device__ __forceinline__ void cp16(uint32_t dst, const void* src) {
    asm volatile("cp.async.cg.shared.global [%0], [%1], 16;" :: "r"(dst), "l"(src));
}
__device__ __forceinline__ void cp_commit() {
    asm volatile("cp.async.commit_group;" ::: "memory");
}
template <int N>
__device__ __forceinline__ void cp_wait() {
    asm volatile("cp.async.wait_group %0;" :: "n"(N) : "memory");
}
__device__ __forceinline__ void mma_tf32(float* d, const float* a, const float* b) {
    asm volatile(
        "mma.sync.aligned.m16n8k8.row.col.f32.tf32.tf32.f32 "
        "{%0,%1,%2,%3}, {%4,%5,%6,%7}, {%8,%9}, {%0,%1,%2,%3};"
        : "+f"(d[0]), "+f"(d[1]), "+f"(d[2]), "+f"(d[3])
        : "r"(__float_as_uint(a[0])), "r"(__float_as_uint(a[1])),
          "r"(__float_as_uint(a[2])), "r"(__float_as_uint(a[3])),
          "r"(__float_as_uint(b[0])), "r"(__float_as_uint(b[1])));
}

// ---------------------------------------------------------------------------
// Kernel 1: pooling (tf32-rounded output). One block per anchor, 64 threads.
// ---------------------------------------------------------------------------
__global__ __launch_bounds__(64) void pool_kernel(
    const float* __restrict__ h_states, const float* __restrict__ end_pos, int P)
{
    int i = blockIdx.x, s = i / P, p = i % P, t = threadIdx.x;

    __shared__ float  sh_hidden[PP * H_DIM];
    __shared__ float2 sh_pos[PP];
    __shared__ int    sh_cell[PP];
    __shared__ float  sh_pool[G2 * H_DIM];

    const float* hseq = h_states + (size_t)s * P * H_DIM;
    #pragma unroll
    for (int k = t; k < PP * H_DIM; k += 64) sh_hidden[k] = hseq[k];
    if (t < PP) sh_pos[t] = ((const float2*)end_pos)[(size_t)s * P + t];
    __syncthreads();

    float px = sh_pos[p].x, py = sh_pos[p].y;
    float tlx = px - 1.0f, tly = py + 1.0f;
    float brx = px + 1.0f, bry = py - 1.0f;

    if (t < PP) {
        float ox = sh_pos[t].x, oy = sh_pos[t].y;
        bool oob = (ox >= brx) || (ox <= tlx) || (oy >= tly) || (oy <= bry) || (t == p);
        int cx = (int)floorf((ox - tlx) / 2.0f * 8.0f);
        int cy = (int)floorf((tly - oy) / 2.0f * 8.0f);
        int c = cx + cy * 8;
        sh_cell[t] = (oob || c < 0 || c >= G2) ? -1 : c;
    }
    #pragma unroll
    for (int k = t; k < G2 * H_DIM; k += 64) sh_pool[k] = 0.0f;
    __syncthreads();

    for (int j = 0; j < PP; j++) {
        int c = sh_cell[j];
        if (c >= 0) sh_pool[c * H_DIM + t] += sh_hidden[j * H_DIM + t];
    }
    __syncthreads();

    float4*       dst = (float4*)(g_pooled + (size_t)i * (G2 * H_DIM));
    const float4* src = (const float4*)sh_pool;
    #pragma unroll
    for (int k = t; k < (G2 * H_DIM) / 4; k += 64) {
        float4 v = src[k];
        v.x = to_tf32(v.x); v.y = to_tf32(v.y);
        v.z = to_tf32(v.z); v.w = to_tf32(v.w);
        dst[k] = v;
    }
}

// ---------------------------------------------------------------------------
// Kernel 2: elementwise tf32 rounding of W into g_Wr (layout unchanged [K,N]).
// ---------------------------------------------------------------------------
__global__ __launch_bounds__(256) void round_w_kernel(const float4* __restrict__ W)
{
    int n4 = (K_TOT * N_TOT) / 4;
    float4* out = (float4*)g_Wr;
    for (int i = blockIdx.x * 256 + threadIdx.x; i < n4; i += gridDim.x * 256) {
        float4 v = W[i];
        v.x = to_tf32(v.x); v.y = to_tf32(v.y);
        v.z = to_tf32(v.z); v.w = to_tf32(v.w);
        out[i] = v;
    }
}

// ---------------------------------------------------------------------------
// Kernel 3: C = relu(A @ W + bias) with mma.sync tf32 m16n8k8.
// Grid (N/128, M/128) = (8, 32), 256 threads, 8 warps as 4(M) x 2(N),
// warp tile 32x64. 3-stage cp.async pipeline.
// ---------------------------------------------------------------------------
__global__ __launch_bounds__(256, 2) void gemm_mma(
    const float* __restrict__ bias, float* __restrict__ C)
{
    extern __shared__ __align__(16) float smem[];

    const int tid = threadIdx.x;
    const int wid = tid >> 5, lane = tid & 31;
    const int g = lane >> 2, tig = lane & 3;      // groupID, thread-in-group
    const int warp_m = wid & 3, warp_n = wid >> 2;
    const int bm0 = blockIdx.y * BM, bn0 = blockIdx.x * BN;

    float acc[2][8][4];
    #pragma unroll
    for (int mt = 0; mt < 2; mt++)
        #pragma unroll
        for (int nt = 0; nt < 8; nt++)
            #pragma unroll
            for (int r = 0; r < 4; r++) acc[mt][nt][r] = 0.0f;

    const uint32_t sbase = smem_u32(smem);

    // stage loader: A tile 128x32 (1024 vec4), B tile 32x128 (1024 vec4)
    auto load_stage = [&](int s, int c) {
        const int k0 = c * BKK;
        uint32_t sa = sbase + (uint32_t)(s * STAGE_FLOATS) * 4u;
        uint32_t sb = sa + (uint32_t)(BM * AS_STRIDE) * 4u;
        #pragma unroll
        for (int i = 0; i < 4; i++) {
            int idx = tid + i * 256;
            int row = idx >> 3, v = idx & 7;        // A: 8 vec4 per row
            cp16(sa + (uint32_t)(row * AS_STRIDE + v * 4) * 4u,
                 g_pooled + (size_t)(bm0 + row) * K_TOT + k0 + v * 4);
        }
        #pragma unroll
        for (int i = 0; i < 4; i++) {
            int idx = tid + i * 256;
            int row = idx >> 5, v = idx & 31;       // B: 32 vec4 per row
            cp16(sb + (uint32_t)(row * BS_STRIDE + v * 4) * 4u,
                 g_Wr + (size_t)(k0 + row) * N_TOT + bn0 + v * 4);
        }
        cp_commit();
    };

    load_stage(0, 0);
    load_stage(1, 1);

    for (int c = 0; c < NC; c++) {
        cp_wait<1>();
        __syncthreads();

        if (c + 2 < NC) load_stage((c + 2) % NST, c + 2);

        const float* As = smem + (c % NST) * STAGE_FLOATS;
        const float* Bs = As + BM * AS_STRIDE;

        #pragma unroll
        for (int ks = 0; ks < BKK / 8; ks++) {
            float a[2][4], b[8][2];
            #pragma unroll
            for (int mt = 0; mt < 2; mt++) {
                int r0 = warp_m * 32 + mt * 16 + g;
                int kk = ks * 8 + tig;
                a[mt][0] = As[r0 * AS_STRIDE + kk];
                a[mt][1] = As[(r0 + 8) * AS_STRIDE + kk];
                a[mt][2] = As[r0 * AS_STRIDE + kk + 4];
                a[mt][3] = As[(r0 + 8) * AS_STRIDE + kk + 4];
            }
            #pragma unroll
            for (int nt = 0; nt < 8; nt++) {
                int col = warp_n * 64 + nt * 8 + g;
                int kk = ks * 8 + tig;
                b[nt][0] = Bs[kk * BS_STRIDE + col];
                b[nt][1] = Bs[(kk + 4) * BS_STRIDE + col];
            }
            #pragma unroll
            for (int mt = 0; mt < 2; mt++)
                #pragma unroll
                for (int nt = 0; nt < 8; nt++)
                    mma_tf32(acc[mt][nt], a[mt], b[nt]);
        }
        __syncthreads();
    }

    // epilogue: bias + relu, float2 stores
    #pragma unroll
    for (int mt = 0; mt < 2; mt++) {
        int r0 = bm0 + warp_m * 32 + mt * 16 + g;
        #pragma unroll
        for (int nt = 0; nt < 8; nt++) {
            int col = bn0 + warp_n * 64 + nt * 8 + tig * 2;
            float b0 = __ldg(bias + col), b1 = __ldg(bias + col + 1);
            float2 v0, v1;
            v0.x = fmaxf(acc[mt][nt][0] + b0, 0.0f);
            v0.y = fmaxf(acc[mt][nt][1] + b1, 0.0f);
            v1.x = fmaxf(acc[mt][nt][2] + b0, 0.0f);
            v1.y = fmaxf(acc[mt][nt][3] + b1, 0.0f);
            *(float2*)(C + (size_t)r0 * N_TOT + col) = v0;
            *(float2*)(C + (size_t)(r0 + 8) * N_TOT + col) = v1;
        }
    }
}

// ---------------------------------------------------------------------------
// Launch
// ---------------------------------------------------------------------------
extern "C" void kernel_launch(void* const* d_in, const int* in_sizes, int n_in,
                              void* d_out, int out_size)
{
    const float* h_states = (const float*)d_in[0];
    const float* end_pos  = (const float*)d_in[2];
    const float* W        = (const float*)d_in[4];
    const float* bias     = (const float*)d_in[5];
    float* out = (float*)d_out;

    int S = in_sizes[1] / 2;   // 64
    int B = in_sizes[2] / 2;   // 4096
    int P = B / S;             // 64

    pool_kernel<<<B, 64>>>(h_states, end_pos, P);
    round_w_kernel<<<1024, 256>>>((const float4*)W);

    static int smem_set = 0;
    if (!smem_set) {
        cudaFuncSetAttribute(gemm_mma, cudaFuncAttributeMaxDynamicSharedMemorySize,
                             SMEM_BYTES);
        smem_set = 1;
    }
    gemm_mma<<<dim3(N_TOT / BN, M_TOT / BM), 256, SMEM_BYTES>>>(bias, out);
}

// round 6
// speedup vs baseline: 5.2553x; 1.6843x over previous
#include <cuda_runtime.h>
#include <cuda_fp16.h>
#include <cstdint>

// ---------------------------------------------------------------------------
// SocialPooling: pooled[i] = scatter-add of neighbor hidden states into an
// 8x8 grid around anchor i, then out = relu(pooled @ W + b).
// Fixed instance: S=64, P=64, B=4096, H=64, g2=64 -> K=4096, N=1024.
// Round 4: fp16 mma.sync m16n8k16 + ldmatrix feed (2x tf32 rate, same
// 10-bit mantissa => same accuracy class).
// ---------------------------------------------------------------------------

#define H_DIM 64
#define G2    64
#define PP    64

#define M_TOT 4096
#define N_TOT 1024
#define K_TOT 4096

#define BM 128
#define BN 128
#define BKF 32                  // fp16 k per chunk (2 k16 steps)
#define NST 4
#define NC (K_TOT / BKF)        // 128 chunks

#define LDAH 40                       // fp16 row stride (80B): row*20 mod 32 -> 8 distinct banks
#define A_BYTES (BM * LDAH * 2)       // 10240
#define STAGE_BYTES (2 * BM * LDAH * 2)   // A + B = 20480
#define SMEM_BYTES (NST * STAGE_BYTES)    // 81920

// scratch: fp16 pooled A (32 MB) + fp16 W^T [N,K] (8 MB)
__device__ __half g_poolh[(size_t)M_TOT * K_TOT];
__device__ __half g_Wth[(size_t)N_TOT * K_TOT];

// ---------------------------------------------------------------------------
// helpers
// ---------------------------------------------------------------------------
__device__ __forceinline__ uint32_t smem_u32(const void* p) {
    uint32_t a;
    asm("{ .reg .u64 t; cvta.to.shared.u64 t, %1; cvt.u32.u64 %0, t; }" : "=r"(a) : "l"(p));
    return a;
}
__device__ __forceinline__ void cp16(uint32_t dst, const void* src) {
    asm volatile("cp.async.cg.shared.global [%0], [%1], 16;" :: "r"(dst), "l"(src));
}
__device__ __forceinline__ void cp_commit() {
    asm volatile("cp.async.commit_group;" ::: "memory");
}
template <int N>
__device__ __forceinline__ void cp_wait() {
    asm volatile("cp.async.wait_group %0;" :: "n"(N) : "memory");
}
__device__ __forceinline__ void ldsm4(uint32_t* r, uint32_t addr) {
    asm volatile("ldmatrix.sync.aligned.m8n8.x4.shared.b16 {%0,%1,%2,%3}, [%4];"
                 : "=r"(r[0]), "=r"(r[1]), "=r"(r[2]), "=r"(r[3]) : "r"(addr));
}
__device__ __forceinline__ void mma16816(float* d, const uint32_t* a,
                                         uint32_t b0, uint32_t b1) {
    asm volatile(
        "mma.sync.aligned.m16n8k16.row.col.f32.f16.f16.f32 "
        "{%0,%1,%2,%3}, {%4,%5,%6,%7}, {%8,%9}, {%0,%1,%2,%3};"
        : "+f"(d[0]), "+f"(d[1]), "+f"(d[2]), "+f"(d[3])
        : "r"(a[0]), "r"(a[1]), "r"(a[2]), "r"(a[3]), "r"(b0), "r"(b1));
}

// ---------------------------------------------------------------------------
// Kernel 1: pooling -> fp16 output. One block per anchor, 64 threads.
// ---------------------------------------------------------------------------
__global__ __launch_bounds__(64) void pool_kernel(
    const float* __restrict__ h_states, const float* __restrict__ end_pos, int P)
{
    int i = blockIdx.x, s = i / P, p = i % P, t = threadIdx.x;

    __shared__ float  sh_hidden[PP * H_DIM];
    __shared__ float2 sh_pos[PP];
    __shared__ int    sh_cell[PP];
    __shared__ float  sh_pool[G2 * H_DIM];

    const float* hseq = h_states + (size_t)s * P * H_DIM;
    #pragma unroll
    for (int k = t; k < PP * H_DIM; k += 64) sh_hidden[k] = hseq[k];
    if (t < PP) sh_pos[t] = ((const float2*)end_pos)[(size_t)s * P + t];
    __syncthreads();

    float px = sh_pos[p].x, py = sh_pos[p].y;
    float tlx = px - 1.0f, tly = py + 1.0f;
    float brx = px + 1.0f, bry = py - 1.0f;

    if (t < PP) {
        float ox = sh_pos[t].x, oy = sh_pos[t].y;
        bool oob = (ox >= brx) || (ox <= tlx) || (oy >= tly) || (oy <= bry) || (t == p);
        int cx = (int)floorf((ox - tlx) / 2.0f * 8.0f);
        int cy = (int)floorf((tly - oy) / 2.0f * 8.0f);
        int c = cx + cy * 8;
        sh_cell[t] = (oob || c < 0 || c >= G2) ? -1 : c;
    }
    #pragma unroll
    for (int k = t; k < G2 * H_DIM; k += 64) sh_pool[k] = 0.0f;
    __syncthreads();

    for (int j = 0; j < PP; j++) {
        int c = sh_cell[j];
        if (c >= 0) sh_pool[c * H_DIM + t] += sh_hidden[j * H_DIM + t];
    }
    __syncthreads();

    // convert to fp16 (RN) and store: 4096 halves = 1024 x 8B
    uint2* dst = (uint2*)(g_poolh + (size_t)i * (G2 * H_DIM));
    const float4* src = (const float4*)sh_pool;
    #pragma unroll
    for (int k = t; k < (G2 * H_DIM) / 4; k += 64) {
        float4 v = src[k];
        __half2 h0 = __floats2half2_rn(v.x, v.y);
        __half2 h1 = __floats2half2_rn(v.z, v.w);
        uint2 u;
        u.x = *reinterpret_cast<uint32_t*>(&h0);
        u.y = *reinterpret_cast<uint32_t*>(&h1);
        dst[k] = u;
    }
}

// ---------------------------------------------------------------------------
// Kernel 2: W[K,N] fp32 -> Wt[N,K] fp16 (transpose + convert). 32x32 tiles.
// ---------------------------------------------------------------------------
__global__ __launch_bounds__(256) void transpose_kernel(const float* __restrict__ W)
{
    __shared__ float tile[32][33];
    int tx = threadIdx.x, ty = threadIdx.y;     // (32, 8)
    int n0 = blockIdx.x * 32, k0 = blockIdx.y * 32;

    #pragma unroll
    for (int i = 0; i < 4; i++) {
        int r = ty + i * 8;
        tile[r][tx] = W[(size_t)(k0 + r) * N_TOT + n0 + tx];
    }
    __syncthreads();
    #pragma unroll
    for (int i = 0; i < 4; i++) {
        int r = ty + i * 8;
        g_Wth[(size_t)(n0 + r) * K_TOT + k0 + tx] = __float2half_rn(tile[tx][r]);
    }
}

// ---------------------------------------------------------------------------
// Kernel 3: C = relu(A @ W + bias), fp16 mma m16n8k16, f32 accumulate.
// Grid (8, 32), 256 threads, 8 warps = 4(M) x 2(N), warp tile 32x64.
// 4-stage cp.async pipeline, ldmatrix fragment feed, 1 barrier per chunk.
// ---------------------------------------------------------------------------
__global__ __launch_bounds__(256, 2) void gemm_hmma(
    const float* __restrict__ bias, float* __restrict__ C)
{
    extern __shared__ __align__(16) __half smem[];

    const int tid = threadIdx.x;
    const int wid = tid >> 5, lane = tid & 31;
    const int g = lane >> 2, tig = lane & 3;
    const int warp_m = wid & 3, warp_n = wid >> 2;
    const int bm0 = blockIdx.y * BM, bn0 = blockIdx.x * BN;

    float acc[2][8][4];
    #pragma unroll
    for (int mt = 0; mt < 2; mt++)
        #pragma unroll
        for (int nt = 0; nt < 8; nt++)
            #pragma unroll
            for (int r = 0; r < 4; r++) acc[mt][nt][r] = 0.0f;

    const uint32_t sbase = smem_u32(smem);

    // stage loader: A tile 128 rows x 32 fp16 (4 x 16B per row), B same
    auto load_stage = [&](int s, int c) {
        const int k0 = c * BKF;
        uint32_t sa = sbase + (uint32_t)(s * STAGE_BYTES);
        uint32_t sb = sa + A_BYTES;
        #pragma unroll
        for (int i = 0; i < 2; i++) {
            int idx = tid + i * 256;
            int row = idx >> 2, v = idx & 3;
            cp16(sa + (uint32_t)(row * (LDAH * 2) + v * 16),
                 g_poolh + (size_t)(bm0 + row) * K_TOT + k0 + v * 8);
        }
        #pragma unroll
        for (int i = 0; i < 2; i++) {
            int idx = tid + i * 256;
            int row = idx >> 2, v = idx & 3;
            cp16(sb + (uint32_t)(row * (LDAH * 2) + v * 16),
                 g_Wth + (size_t)(bn0 + row) * K_TOT + k0 + v * 8);
        }
        cp_commit();
    };

    load_stage(0, 0);
    load_stage(1, 1);
    load_stage(2, 2);

    const int q = lane >> 3, r8 = lane & 7;   // ldmatrix address roles

    for (int c = 0; c < NC; c++) {
        cp_wait<2>();
        __syncthreads();

        if (c + 3 < NC) load_stage((c + 3) % NST, c + 3);

        uint32_t sa = sbase + (uint32_t)((c % NST) * STAGE_BYTES);
        uint32_t sb = sa + A_BYTES;

        #pragma unroll
        for (int ks = 0; ks < 2; ks++) {
            const int k0 = ks * 16;
            uint32_t a[2][4], b[4][4];
            #pragma unroll
            for (int mt = 0; mt < 2; mt++) {
                int row = warp_m * 32 + mt * 16 + (q & 1) * 8 + r8;
                int col = k0 + (q >> 1) * 8;
                ldsm4(a[mt], sa + (uint32_t)(row * (LDAH * 2) + col * 2));
            }
            #pragma unroll
            for (int nb = 0; nb < 4; nb++) {
                int row = warp_n * 64 + nb * 16 + (q >> 1) * 8 + r8;
                int col = k0 + (q & 1) * 8;
                ldsm4(b[nb], sb + (uint32_t)(row * (LDAH * 2) + col * 2));
            }
            #pragma unroll
            for (int mt = 0; mt < 2; mt++)
                #pragma unroll
                for (int nb = 0; nb < 4; nb++) {
                    mma16816(acc[mt][2 * nb],     a[mt], b[nb][0], b[nb][1]);
                    mma16816(acc[mt][2 * nb + 1], a[mt], b[nb][2], b[nb][3]);
                }
        }
    }

    // epilogue: bias + relu, float2 stores
    #pragma unroll
    for (int mt = 0; mt < 2; mt++) {
        int r0 = bm0 + warp_m * 32 + mt * 16 + g;
        #pragma unroll
        for (int nt = 0; nt < 8; nt++) {
            int col = bn0 + warp_n * 64 + nt * 8 + tig * 2;
            float b0 = __ldg(bias + col), b1 = __ldg(bias + col + 1);
            float2 v0, v1;
            v0.x = fmaxf(acc[mt][nt][0] + b0, 0.0f);
            v0.y = fmaxf(acc[mt][nt][1] + b1, 0.0f);
            v1.x = fmaxf(acc[mt][nt][2] + b0, 0.0f);
            v1.y = fmaxf(acc[mt][nt][3] + b1, 0.0f);
            *(float2*)(C + (size_t)r0 * N_TOT + col) = v0;
            *(float2*)(C + (size_t)(r0 + 8) * N_TOT + col) = v1;
        }
    }
}

// ---------------------------------------------------------------------------
// Launch
// ---------------------------------------------------------------------------
extern "C" void kernel_launch(void* const* d_in, const int* in_sizes, int n_in,
                              void* d_out, int out_size)
{
    const float* h_states = (const float*)d_in[0];
    const float* end_pos  = (const float*)d_in[2];
    const float* W        = (const float*)d_in[4];
    const float* bias     = (const float*)d_in[5];
    float* out = (float*)d_out;

    int S = in_sizes[1] / 2;   // 64
    int B = in_sizes[2] / 2;   // 4096
    int P = B / S;             // 64

    pool_kernel<<<B, 64>>>(h_states, end_pos, P);
    transpose_kernel<<<dim3(N_TOT / 32, K_TOT / 32), dim3(32, 8)>>>(W);

    static int smem_set = 0;
    if (!smem_set) {
        cudaFuncSetAttribute(gemm_hmma, cudaFuncAttributeMaxDynamicSharedMemorySize,
                             SMEM_BYTES);
        smem_set = 1;
    }
    gemm_hmma<<<dim3(N_TOT / BN, M_TOT / BM), 256, SMEM_BYTES>>>(bias, out);
}

// round 7
// speedup vs baseline: 6.3121x; 1.2011x over previous
#include <cuda_runtime.h>
#include <cuda_fp16.h>
#include <cstdint>

// ---------------------------------------------------------------------------
// SocialPooling: pooled[i] = scatter-add of neighbor hidden states into an
// 8x8 grid around anchor i, then out = relu(pooled @ W + b).
// Fixed instance: S=64, P=64, B=4096, H=64, g2=64 -> K=4096, N=1024.
// Round 7: GEMM re-tiled to 4 warps / 64x64 warp tiles (MMA:ldsm 4.0);
// pool kernel: 2 anchors per 256-thread block, split accumulation chains.
// ---------------------------------------------------------------------------

#define H_DIM 64
#define G2    64
#define PP    64

#define M_TOT 4096
#define N_TOT 1024
#define K_TOT 4096

#define BM 128
#define BN 128
#define BKF 32
#define NST 4
#define NC (K_TOT / BKF)

#define LDAH 40                          // fp16 row stride (80B)
#define A_BYTES (BM * LDAH * 2)          // 10240
#define STAGE_BYTES (2 * BM * LDAH * 2)  // 20480
#define SMEM_GEMM (NST * STAGE_BYTES)    // 81920

// pool kernel dynamic smem layout (bytes)
#define PK_HID  0            // 4096 f32
#define PK_POS  16384        // 64 float2
#define PK_CELL 16896        // 2 x 64 int
#define PK_BUF  17408        // 2 anchors x 2 splits x 4096 f32
#define SMEM_POOL (17408 + 4 * 4096 * 4)   // 82944

// scratch: fp16 pooled A (32 MB) + fp16 W^T [N,K] (8 MB)
__device__ __half g_poolh[(size_t)M_TOT * K_TOT];
__device__ __half g_Wth[(size_t)N_TOT * K_TOT];

// ---------------------------------------------------------------------------
// helpers
// ---------------------------------------------------------------------------
__device__ __forceinline__ uint32_t smem_u32(const void* p) {
    uint32_t a;
    asm("{ .reg .u64 t; cvta.to.shared.u64 t, %1; cvt.u32.u64 %0, t; }" : "=r"(a) : "l"(p));
    return a;
}
__device__ __forceinline__ void cp16(uint32_t dst, const void* src) {
    asm volatile("cp.async.cg.shared.global [%0], [%1], 16;" :: "r"(dst), "l"(src));
}
__device__ __forceinline__ void cp_commit() {
    asm volatile("cp.async.commit_group;" ::: "memory");
}
template <int N>
__device__ __forceinline__ void cp_wait() {
    asm volatile("cp.async.wait_group %0;" :: "n"(N) : "memory");
}
__device__ __forceinline__ void ldsm4(uint32_t* r, uint32_t addr) {
    asm volatile("ldmatrix.sync.aligned.m8n8.x4.shared.b16 {%0,%1,%2,%3}, [%4];"
                 : "=r"(r[0]), "=r"(r[1]), "=r"(r[2]), "=r"(r[3]) : "r"(addr));
}
__device__ __forceinline__ void mma16816(float* d, const uint32_t* a,
                                         uint32_t b0, uint32_t b1) {
    asm volatile(
        "mma.sync.aligned.m16n8k16.row.col.f32.f16.f16.f32 "
        "{%0,%1,%2,%3}, {%4,%5,%6,%7}, {%8,%9}, {%0,%1,%2,%3};"
        : "+f"(d[0]), "+f"(d[1]), "+f"(d[2]), "+f"(d[3])
        : "r"(a[0]), "r"(a[1]), "r"(a[2]), "r"(a[3]), "r"(b0), "r"(b1));
}

// ---------------------------------------------------------------------------
// Kernel 1: pooling -> fp16. 2 anchors per block, 256 threads.
// thread = (anchor a = tid>>7, split s2 = (tid>>6)&1, dim t = tid&63).
// Each (a,s2,t) accumulates j in [s2*32, s2*32+32) into its own buffer;
// buffers summed at writeout. Halves the smem RAW chain, shares hidden.
// ---------------------------------------------------------------------------
__global__ __launch_bounds__(256) void pool_kernel(
    const float* __restrict__ h_states, const float* __restrict__ end_pos, int P)
{
    extern __shared__ __align__(16) char psm[];
    float*  sh_hidden = (float*)(psm + PK_HID);
    float2* sh_pos    = (float2*)(psm + PK_POS);
    int*    sh_cell   = (int*)(psm + PK_CELL);      // [2][64]
    float*  sh_buf    = (float*)(psm + PK_BUF);     // [2][2][4096]

    const int blk = blockIdx.x;
    const int s   = blk >> 5;          // 32 blocks per sequence
    const int a0  = (blk & 31) * 2;    // first anchor (person) index
    const int tid = threadIdx.x;
    const int a   = tid >> 7;          // anchor 0/1
    const int s2  = (tid >> 6) & 1;    // j-split
    const int t   = tid & 63;          // hidden dim

    // load hidden (4096 f32) + positions
    const float4* hseq = (const float4*)(h_states + (size_t)s * PP * H_DIM);
    #pragma unroll
    for (int k = tid; k < PP * H_DIM / 4; k += 256)
        ((float4*)sh_hidden)[k] = hseq[k];
    if (tid < PP) sh_pos[tid] = ((const float2*)end_pos)[(size_t)s * PP + tid];
    // zero the 4 accumulation buffers (4096 float4)
    #pragma unroll
    for (int k = tid; k < 4 * 4096 / 4; k += 256)
        ((float4*)sh_buf)[k] = make_float4(0.f, 0.f, 0.f, 0.f);
    __syncthreads();

    // cells: threads 0..127 -> (anchor aa, neighbor j)
    if (tid < 128) {
        int aa = tid >> 6, j = tid & 63;
        int p = a0 + aa;
        float px = sh_pos[p].x, py = sh_pos[p].y;
        float tlx = px - 1.0f, tly = py + 1.0f;
        float brx = px + 1.0f, bry = py - 1.0f;
        float ox = sh_pos[j].x, oy = sh_pos[j].y;
        bool oob = (ox >= brx) || (ox <= tlx) || (oy >= tly) || (oy <= bry) || (j == p);
        int cx = (int)floorf((ox - tlx) / 2.0f * 8.0f);
        int cy = (int)floorf((tly - oy) / 2.0f * 8.0f);
        int c = cx + cy * 8;
        sh_cell[aa * 64 + j] = (oob || c < 0 || c >= G2) ? -1 : c;
    }
    __syncthreads();

    // scatter-accumulate: 32-deep chain per thread
    {
        float* buf = sh_buf + (a * 2 + s2) * 4096;
        const int jb = s2 * 32;
        #pragma unroll 4
        for (int j = 0; j < 32; j++) {
            int c = sh_cell[a * 64 + jb + j];
            if (c >= 0) buf[c * H_DIM + t] += sh_hidden[(jb + j) * H_DIM + t];
        }
    }
    __syncthreads();

    // writeout: 128 threads per anchor sum the two split buffers -> fp16
    {
        int aa = tid >> 7, lt = tid & 127;
        const float4* b0 = (const float4*)(sh_buf + (aa * 2 + 0) * 4096);
        const float4* b1 = (const float4*)(sh_buf + (aa * 2 + 1) * 4096);
        uint2* dst = (uint2*)(g_poolh + (size_t)(s * PP + a0 + aa) * (G2 * H_DIM));
        #pragma unroll
        for (int k = lt; k < 4096 / 4; k += 128) {
            float4 v0 = b0[k], v1 = b1[k];
            __half2 h0 = __floats2half2_rn(v0.x + v1.x, v0.y + v1.y);
            __half2 h1 = __floats2half2_rn(v0.z + v1.z, v0.w + v1.w);
            uint2 u;
            u.x = *reinterpret_cast<uint32_t*>(&h0);
            u.y = *reinterpret_cast<uint32_t*>(&h1);
            dst[k] = u;
        }
    }
}

// ---------------------------------------------------------------------------
// Kernel 2: W[K,N] fp32 -> Wt[N,K] fp16 (transpose + convert). 32x32 tiles.
// ---------------------------------------------------------------------------
__global__ __launch_bounds__(256) void transpose_kernel(const float* __restrict__ W)
{
    __shared__ float tile[32][33];
    int tx = threadIdx.x, ty = threadIdx.y;     // (32, 8)
    int n0 = blockIdx.x * 32, k0 = blockIdx.y * 32;

    #pragma unroll
    for (int i = 0; i < 4; i++) {
        int r = ty + i * 8;
        tile[r][tx] = W[(size_t)(k0 + r) * N_TOT + n0 + tx];
    }
    __syncthreads();
    #pragma unroll
    for (int i = 0; i < 4; i++) {
        int r = ty + i * 8;
        g_Wth[(size_t)(n0 + r) * K_TOT + k0 + tx] = __float2half_rn(tile[tx][r]);
    }
}

// ---------------------------------------------------------------------------
// Kernel 3: C = relu(A @ W + bias), fp16 mma m16n8k16, f32 accumulate.
// 128 threads = 4 warps as 2(M) x 2(N), warp tile 64x64.
// 4-stage cp.async pipeline, ldmatrix feed (8 ldsm : 32 MMA per k16).
// ---------------------------------------------------------------------------
__global__ __launch_bounds__(128, 2) void gemm_hmma(
    const float* __restrict__ bias, float* __restrict__ C)
{
    extern __shared__ __align__(16) __half smem[];

    const int tid = threadIdx.x;
    const int wid = tid >> 5, lane = tid & 31;
    const int g = lane >> 2, tig = lane & 3;
    const int warp_m = wid & 1, warp_n = wid >> 1;
    const int bm0 = blockIdx.y * BM, bn0 = blockIdx.x * BN;

    float acc[4][8][4];
    #pragma unroll
    for (int mt = 0; mt < 4; mt++)
        #pragma unroll
        for (int nt = 0; nt < 8; nt++)
            #pragma unroll
            for (int r = 0; r < 4; r++) acc[mt][nt][r] = 0.0f;

    const uint32_t sbase = smem_u32(smem);

    // stage loader: A tile 128 rows x 4 x 16B, B same; 128 threads
    auto load_stage = [&](int st, int c) {
        const int k0 = c * BKF;
        uint32_t sa = sbase + (uint32_t)(st * STAGE_BYTES);
        uint32_t sb = sa + A_BYTES;
        #pragma unroll
        for (int i = 0; i < 4; i++) {
            int idx = tid + i * 128;
            int row = idx >> 2, v = idx & 3;
            cp16(sa + (uint32_t)(row * (LDAH * 2) + v * 16),
                 g_poolh + (size_t)(bm0 + row) * K_TOT + k0 + v * 8);
        }
        #pragma unroll
        for (int i = 0; i < 4; i++) {
            int idx = tid + i * 128;
            int row = idx >> 2, v = idx & 3;
            cp16(sb + (uint32_t)(row * (LDAH * 2) + v * 16),
                 g_Wth + (size_t)(bn0 + row) * K_TOT + k0 + v * 8);
        }
        cp_commit();
    };

    load_stage(0, 0);
    load_stage(1, 1);
    load_stage(2, 2);

    const int q = lane >> 3, r8 = lane & 7;

    for (int c = 0; c < NC; c++) {
        cp_wait<2>();
        __syncthreads();

        if (c + 3 < NC) load_stage((c + 3) % NST, c + 3);

        uint32_t sa = sbase + (uint32_t)((c % NST) * STAGE_BYTES);
        uint32_t sb = sa + A_BYTES;

        #pragma unroll
        for (int ks = 0; ks < 2; ks++) {
            const int k0 = ks * 16;
            uint32_t a[4][4], b[4][4];
            #pragma unroll
            for (int mt = 0; mt < 4; mt++) {
                int row = warp_m * 64 + mt * 16 + (q & 1) * 8 + r8;
                int col = k0 + (q >> 1) * 8;
                ldsm4(a[mt], sa + (uint32_t)(row * (LDAH * 2) + col * 2));
            }
            #pragma unroll
            for (int nb = 0; nb < 4; nb++) {
                int row = warp_n * 64 + nb * 16 + (q >> 1) * 8 + r8;
                int col = k0 + (q & 1) * 8;
                ldsm4(b[nb], sb + (uint32_t)(row * (LDAH * 2) + col * 2));
            }
            #pragma unroll
            for (int mt = 0; mt < 4; mt++)
                #pragma unroll
                for (int nb = 0; nb < 4; nb++) {
                    mma16816(acc[mt][2 * nb],     a[mt], b[nb][0], b[nb][1]);
                    mma16816(acc[mt][2 * nb + 1], a[mt], b[nb][2], b[nb][3]);
                }
        }
    }

    // epilogue: bias + relu, float2 stores
    #pragma unroll
    for (int mt = 0; mt < 4; mt++) {
        int r0 = bm0 + warp_m * 64 + mt * 16 + g;
        #pragma unroll
        for (int nt = 0; nt < 8; nt++) {
            int col = bn0 + warp_n * 64 + nt * 8 + tig * 2;
            float b0 = __ldg(bias + col), b1 = __ldg(bias + col + 1);
            float2 v0, v1;
            v0.x = fmaxf(acc[mt][nt][0] + b0, 0.0f);
            v0.y = fmaxf(acc[mt][nt][1] + b1, 0.0f);
            v1.x = fmaxf(acc[mt][nt][2] + b0, 0.0f);
            v1.y = fmaxf(acc[mt][nt][3] + b1, 0.0f);
            *(float2*)(C + (size_t)r0 * N_TOT + col) = v0;
            *(float2*)(C + (size_t)(r0 + 8) * N_TOT + col) = v1;
        }
    }
}

// ---------------------------------------------------------------------------
// Launch
// ---------------------------------------------------------------------------
extern "C" void kernel_launch(void* const* d_in, const int* in_sizes, int n_in,
                              void* d_out, int out_size)
{
    const float* h_states = (const float*)d_in[0];
    const float* end_pos  = (const float*)d_in[2];
    const float* W        = (const float*)d_in[4];
    const float* bias     = (const float*)d_in[5];
    float* out = (float*)d_out;

    int S = in_sizes[1] / 2;   // 64
    int B = in_sizes[2] / 2;   // 4096
    int P = B / S;             // 64
    (void)S; (void)P;

    static int attr_set = 0;
    if (!attr_set) {
        cudaFuncSetAttribute(gemm_hmma, cudaFuncAttributeMaxDynamicSharedMemorySize,
                             SMEM_GEMM);
        cudaFuncSetAttribute(pool_kernel, cudaFuncAttributeMaxDynamicSharedMemorySize,
                             SMEM_POOL);
        attr_set = 1;
    }

    pool_kernel<<<B / 2, 256, SMEM_POOL>>>(h_states, end_pos, P);
    transpose_kernel<<<dim3(N_TOT / 32, K_TOT / 32), dim3(32, 8)>>>(W);
    gemm_hmma<<<dim3(N_TOT / BN, M_TOT / BM), 128, SMEM_GEMM>>>(bias, out);
}

// round 8
// speedup vs baseline: 6.5596x; 1.0392x over previous
#include <cuda_runtime.h>
#include <cuda_fp16.h>
#include <cstdint>

// ---------------------------------------------------------------------------
// SocialPooling: pooled[i] = scatter-add of neighbor hidden states into an
// 8x8 grid around anchor i, then out = relu(pooled @ W + b).
// Fixed instance: S=64, P=64, B=4096, H=64, g2=64 -> K=4096, N=1024.
// Round 8: sparsity-aware pool (cell-occupancy mask: only touch occupied
// cells in smem; empty cells get direct zero stores). GEMM unchanged (R7).
// ---------------------------------------------------------------------------

#define H_DIM 64
#define G2    64
#define PP    64

#define M_TOT 4096
#define N_TOT 1024
#define K_TOT 4096

#define BM 128
#define BN 128
#define BKF 32
#define NST 4
#define NC (K_TOT / BKF)

#define LDAH 40                          // fp16 row stride (80B)
#define A_BYTES (BM * LDAH * 2)          // 10240
#define STAGE_BYTES (2 * BM * LDAH * 2)  // 20480
#define SMEM_GEMM (NST * STAGE_BYTES)    // 81920

// pool kernel dynamic smem layout (bytes); 4 anchors per 256-thread block
#define PK_HID  0                 // 4096 f32 = 16384
#define PK_POS  16384             // 64 float2 = 512
#define PK_CELL 16896             // 4 x 64 int = 1024
#define PK_MASK 17920             // 4 x 2 uint32 (+pad) = 128
#define PK_BUF  18048             // 4 x 4096 f32 = 65536
#define SMEM_POOL (PK_BUF + 4 * 4096 * 4)    // 83584

// scratch: fp16 pooled A (32 MB) + fp16 W^T [N,K] (8 MB)
__device__ __half g_poolh[(size_t)M_TOT * K_TOT];
__device__ __half g_Wth[(size_t)N_TOT * K_TOT];

// ---------------------------------------------------------------------------
// helpers
// ---------------------------------------------------------------------------
__device__ __forceinline__ uint32_t smem_u32(const void* p) {
    uint32_t a;
    asm("{ .reg .u64 t; cvta.to.shared.u64 t, %1; cvt.u32.u64 %0, t; }" : "=r"(a) : "l"(p));
    return a;
}
__device__ __forceinline__ void cp16(uint32_t dst, const void* src) {
    asm volatile("cp.async.cg.shared.global [%0], [%1], 16;" :: "r"(dst), "l"(src));
}
__device__ __forceinline__ void cp_commit() {
    asm volatile("cp.async.commit_group;" ::: "memory");
}
template <int N>
__device__ __forceinline__ void cp_wait() {
    asm volatile("cp.async.wait_group %0;" :: "n"(N) : "memory");
}
__device__ __forceinline__ void ldsm4(uint32_t* r, uint32_t addr) {
    asm volatile("ldmatrix.sync.aligned.m8n8.x4.shared.b16 {%0,%1,%2,%3}, [%4];"
                 : "=r"(r[0]), "=r"(r[1]), "=r"(r[2]), "=r"(r[3]) : "r"(addr));
}
__device__ __forceinline__ void mma16816(float* d, const uint32_t* a,
                                         uint32_t b0, uint32_t b1) {
    asm volatile(
        "mma.sync.aligned.m16n8k16.row.col.f32.f16.f16.f32 "
        "{%0,%1,%2,%3}, {%4,%5,%6,%7}, {%8,%9}, {%0,%1,%2,%3};"
        : "+f"(d[0]), "+f"(d[1]), "+f"(d[2]), "+f"(d[3])
        : "r"(a[0]), "r"(a[1]), "r"(a[2]), "r"(a[3]), "r"(b0), "r"(b1));
}

// ---------------------------------------------------------------------------
// Kernel 1: pooling -> fp16, sparsity-aware. 4 anchors per 256-thread block.
// ---------------------------------------------------------------------------
__global__ __launch_bounds__(256) void pool_kernel(
    const float* __restrict__ h_states, const float* __restrict__ end_pos)
{
    extern __shared__ __align__(16) char psm[];
    float*    sh_hidden = (float*)(psm + PK_HID);
    float2*   sh_pos    = (float2*)(psm + PK_POS);
    int*      sh_cell   = (int*)(psm + PK_CELL);     // [4][64]
    uint32_t* sh_mask   = (uint32_t*)(psm + PK_MASK);// [4][2]
    float*    sh_buf    = (float*)(psm + PK_BUF);    // [4][4096]

    const int blk = blockIdx.x;
    const int s   = blk >> 4;          // 16 blocks per sequence
    const int a0  = (blk & 15) * 4;    // first anchor of this block
    const int tid = threadIdx.x;
    const int a   = tid >> 6;          // anchor slot 0..3
    const int t   = tid & 63;          // hidden-dim / neighbor lane

    // load hidden (4096 f32) + positions; clear masks
    const float4* hseq = (const float4*)(h_states + (size_t)s * PP * H_DIM);
    #pragma unroll
    for (int k = tid; k < PP * H_DIM / 4; k += 256)
        ((float4*)sh_hidden)[k] = hseq[k];
    if (tid < PP) sh_pos[tid] = ((const float2*)end_pos)[(size_t)s * PP + tid];
    if (tid < 8) sh_mask[tid] = 0u;
    __syncthreads();

    // cell compute: thread (a, j=t) -> cell id + occupancy mask
    {
        const int p = a0 + a, j = t;
        float px = sh_pos[p].x, py = sh_pos[p].y;
        float tlx = px - 1.0f, tly = py + 1.0f;
        float brx = px + 1.0f, bry = py - 1.0f;
        float ox = sh_pos[j].x, oy = sh_pos[j].y;
        bool oob = (ox >= brx) || (ox <= tlx) || (oy >= tly) || (oy <= bry) || (j == p);
        int cx = (int)floorf((ox - tlx) / 2.0f * 8.0f);
        int cy = (int)floorf((tly - oy) / 2.0f * 8.0f);
        int c = cx + cy * 8;
        bool ok = !oob && c >= 0 && c < G2;
        sh_cell[a * 64 + j] = ok ? c : -1;
        if (ok) atomicOr(&sh_mask[a * 2 + (c >> 5)], 1u << (c & 31));
    }
    __syncthreads();

    const uint32_t m0 = sh_mask[a * 2 + 0], m1 = sh_mask[a * 2 + 1];

    // zero only occupied cells' slots
    {
        float* buf = sh_buf + a * 4096;
        #pragma unroll
        for (int c = 0; c < 32; c++)
            if ((m0 >> c) & 1) buf[c * H_DIM + t] = 0.0f;
        #pragma unroll
        for (int c = 0; c < 32; c++)
            if ((m1 >> c) & 1) buf[(c + 32) * H_DIM + t] = 0.0f;
    }
    __syncthreads();

    // scatter-accumulate
    {
        float* buf = sh_buf + a * 4096;
        const int* cells = sh_cell + a * 64;
        #pragma unroll 4
        for (int j = 0; j < 64; j++) {
            int c = cells[j];
            if (c >= 0) buf[c * H_DIM + t] += sh_hidden[j * H_DIM + t];
        }
    }
    __syncthreads();

    // writeout: per anchor, 2 warps; warp w writes cells {2*ci + w}.
    // occupied -> read buf, convert; empty -> direct zero store. 128B/warp.
    {
        const int w = t >> 5, l = t & 31;
        const float* buf = sh_buf + a * 4096;
        uint32_t* dst = (uint32_t*)(g_poolh + (size_t)(s * PP + a0 + a) * (G2 * H_DIM));
        #pragma unroll
        for (int ci = 0; ci < 32; ci++) {
            int c = ci * 2 + w;
            bool occ = (c < 32) ? ((m0 >> c) & 1) : ((m1 >> (c - 32)) & 1);
            uint32_t u = 0u;
            if (occ) {
                __half2 h = __floats2half2_rn(buf[c * H_DIM + 2 * l],
                                              buf[c * H_DIM + 2 * l + 1]);
                u = *reinterpret_cast<uint32_t*>(&h);
            }
            dst[c * 32 + l] = u;
        }
    }
}

// ---------------------------------------------------------------------------
// Kernel 2: W[K,N] fp32 -> Wt[N,K] fp16 (transpose + convert). 32x32 tiles.
// ---------------------------------------------------------------------------
__global__ __launch_bounds__(256) void transpose_kernel(const float* __restrict__ W)
{
    __shared__ float tile[32][33];
    int tx = threadIdx.x, ty = threadIdx.y;     // (32, 8)
    int n0 = blockIdx.x * 32, k0 = blockIdx.y * 32;

    #pragma unroll
    for (int i = 0; i < 4; i++) {
        int r = ty + i * 8;
        tile[r][tx] = W[(size_t)(k0 + r) * N_TOT + n0 + tx];
    }
    __syncthreads();
    #pragma unroll
    for (int i = 0; i < 4; i++) {
        int r = ty + i * 8;
        g_Wth[(size_t)(n0 + r) * K_TOT + k0 + tx] = __float2half_rn(tile[tx][r]);
    }
}

// ---------------------------------------------------------------------------
// Kernel 3: C = relu(A @ W + bias), fp16 mma m16n8k16, f32 accumulate.
// 128 threads = 4 warps as 2(M) x 2(N), warp tile 64x64. 4-stage cp.async.
// ---------------------------------------------------------------------------
__global__ __launch_bounds__(128, 2) void gemm_hmma(
    const float* __restrict__ bias, float* __restrict__ C)
{
    extern __shared__ __align__(16) __half smem[];

    const int tid = threadIdx.x;
    const int wid = tid >> 5, lane = tid & 31;
    const int g = lane >> 2, tig = lane & 3;
    const int warp_m = wid & 1, warp_n = wid >> 1;
    const int bm0 = blockIdx.y * BM, bn0 = blockIdx.x * BN;

    float acc[4][8][4];
    #pragma unroll
    for (int mt = 0; mt < 4; mt++)
        #pragma unroll
        for (int nt = 0; nt < 8; nt++)
            #pragma unroll
            for (int r = 0; r < 4; r++) acc[mt][nt][r] = 0.0f;

    const uint32_t sbase = smem_u32(smem);

    auto load_stage = [&](int st, int c) {
        const int k0 = c * BKF;
        uint32_t sa = sbase + (uint32_t)(st * STAGE_BYTES);
        uint32_t sb = sa + A_BYTES;
        #pragma unroll
        for (int i = 0; i < 4; i++) {
            int idx = tid + i * 128;
            int row = idx >> 2, v = idx & 3;
            cp16(sa + (uint32_t)(row * (LDAH * 2) + v * 16),
                 g_poolh + (size_t)(bm0 + row) * K_TOT + k0 + v * 8);
        }
        #pragma unroll
        for (int i = 0; i < 4; i++) {
            int idx = tid + i * 128;
            int row = idx >> 2, v = idx & 3;
            cp16(sb + (uint32_t)(row * (LDAH * 2) + v * 16),
                 g_Wth + (size_t)(bn0 + row) * K_TOT + k0 + v * 8);
        }
        cp_commit();
    };

    load_stage(0, 0);
    load_stage(1, 1);
    load_stage(2, 2);

    const int q = lane >> 3, r8 = lane & 7;

    for (int c = 0; c < NC; c++) {
        cp_wait<2>();
        __syncthreads();

        if (c + 3 < NC) load_stage((c + 3) % NST, c + 3);

        uint32_t sa = sbase + (uint32_t)((c % NST) * STAGE_BYTES);
        uint32_t sb = sa + A_BYTES;

        #pragma unroll
        for (int ks = 0; ks < 2; ks++) {
            const int k0 = ks * 16;
            uint32_t a[4][4], b[4][4];
            #pragma unroll
            for (int mt = 0; mt < 4; mt++) {
                int row = warp_m * 64 + mt * 16 + (q & 1) * 8 + r8;
                int col = k0 + (q >> 1) * 8;
                ldsm4(a[mt], sa + (uint32_t)(row * (LDAH * 2) + col * 2));
            }
            #pragma unroll
            for (int nb = 0; nb < 4; nb++) {
                int row = warp_n * 64 + nb * 16 + (q >> 1) * 8 + r8;
                int col = k0 + (q & 1) * 8;
                ldsm4(b[nb], sb + (uint32_t)(row * (LDAH * 2) + col * 2));
            }
            #pragma unroll
            for (int mt = 0; mt < 4; mt++)
                #pragma unroll
                for (int nb = 0; nb < 4; nb++) {
                    mma16816(acc[mt][2 * nb],     a[mt], b[nb][0], b[nb][1]);
                    mma16816(acc[mt][2 * nb + 1], a[mt], b[nb][2], b[nb][3]);
                }
        }
    }

    // epilogue: bias hoisted (loop-invariant over mt), relu, float2 stores
    float2 bb[8];
    #pragma unroll
    for (int nt = 0; nt < 8; nt++) {
        int col = bn0 + warp_n * 64 + nt * 8 + tig * 2;
        bb[nt].x = __ldg(bias + col);
        bb[nt].y = __ldg(bias + col + 1);
    }
    #pragma unroll
    for (int mt = 0; mt < 4; mt++) {
        int r0 = bm0 + warp_m * 64 + mt * 16 + g;
        #pragma unroll
        for (int nt = 0; nt < 8; nt++) {
            int col = bn0 + warp_n * 64 + nt * 8 + tig * 2;
            float2 v0, v1;
            v0.x = fmaxf(acc[mt][nt][0] + bb[nt].x, 0.0f);
            v0.y = fmaxf(acc[mt][nt][1] + bb[nt].y, 0.0f);
            v1.x = fmaxf(acc[mt][nt][2] + bb[nt].x, 0.0f);
            v1.y = fmaxf(acc[mt][nt][3] + bb[nt].y, 0.0f);
            *(float2*)(C + (size_t)r0 * N_TOT + col) = v0;
            *(float2*)(C + (size_t)(r0 + 8) * N_TOT + col) = v1;
        }
    }
}

// ---------------------------------------------------------------------------
// Launch
// ---------------------------------------------------------------------------
extern "C" void kernel_launch(void* const* d_in, const int* in_sizes, int n_in,
                              void* d_out, int out_size)
{
    const float* h_states = (const float*)d_in[0];
    const float* end_pos  = (const float*)d_in[2];
    const float* W        = (const float*)d_in[4];
    const float* bias     = (const float*)d_in[5];
    float* out = (float*)d_out;

    int B = in_sizes[2] / 2;   // 4096

    static int attr_set = 0;
    if (!attr_set) {
        cudaFuncSetAttribute(gemm_hmma, cudaFuncAttributeMaxDynamicSharedMemorySize,
                             SMEM_GEMM);
        cudaFuncSetAttribute(pool_kernel, cudaFuncAttributeMaxDynamicSharedMemorySize,
                             SMEM_POOL);
        attr_set = 1;
    }

    pool_kernel<<<B / 4, 256, SMEM_POOL>>>(h_states, end_pos);
    transpose_kernel<<<dim3(N_TOT / 32, K_TOT / 32), dim3(32, 8)>>>(W);
    gemm_hmma<<<dim3(N_TOT / BN, M_TOT / BM), 128, SMEM_GEMM>>>(bias, out);
}

// round 9
// speedup vs baseline: 7.5665x; 1.1535x over previous
#include <cuda_runtime.h>
#include <cuda_fp16.h>
#include <cstdint>

// ---------------------------------------------------------------------------
// SocialPooling: pooled[i] = scatter-add of neighbor hidden states into an
// 8x8 grid around anchor i, then out = relu(pooled @ W + b).
// Fixed instance: S=64, P=64, B=4096, H=64, g2=64 -> K=4096, N=1024.
// Round 9: linked-list pool (register accumulation, no smem pool buffer),
// fused with the W transpose in one launch. GEMM unchanged (R8).
// ---------------------------------------------------------------------------

#define H_DIM 64
#define G2    64
#define PP    64

#define M_TOT 4096
#define N_TOT 1024
#define K_TOT 4096

#define BM 128
#define BN 128
#define BKF 32
#define NST 4
#define NC (K_TOT / BKF)

#define LDAH 40                          // fp16 row stride (80B)
#define A_BYTES (BM * LDAH * 2)          // 10240
#define STAGE_BYTES (2 * BM * LDAH * 2)  // 20480
#define SMEM_GEMM (NST * STAGE_BYTES)    // 81920

// prep kernel: pool part needs hidden(16384) + pos(512) + head(2048) + next(2048)
#define PA 8                              // anchors per pool block
#define POOL_BLOCKS (M_TOT / PA)          // 512
#define PK_POS  16384
#define PK_HEAD 16896
#define PK_NEXT 18944
#define SMEM_PREP 20992                   // transpose branch needs only 4224

// scratch: fp16 pooled A (32 MB) + fp16 W^T [N,K] (8 MB)
__device__ __half g_poolh[(size_t)M_TOT * K_TOT];
__device__ __half g_Wth[(size_t)N_TOT * K_TOT];

// ---------------------------------------------------------------------------
// helpers
// ---------------------------------------------------------------------------
__device__ __forceinline__ uint32_t smem_u32(const void* p) {
    uint32_t a;
    asm("{ .reg .u64 t; cvta.to.shared.u64 t, %1; cvt.u32.u64 %0, t; }" : "=r"(a) : "l"(p));
    return a;
}
__device__ __forceinline__ void cp16(uint32_t dst, const void* src) {
    asm volatile("cp.async.cg.shared.global [%0], [%1], 16;" :: "r"(dst), "l"(src));
}
__device__ __forceinline__ void cp_commit() {
    asm volatile("cp.async.commit_group;" ::: "memory");
}
template <int N>
__device__ __forceinline__ void cp_wait() {
    asm volatile("cp.async.wait_group %0;" :: "n"(N) : "memory");
}
__device__ __forceinline__ void ldsm4(uint32_t* r, uint32_t addr) {
    asm volatile("ldmatrix.sync.aligned.m8n8.x4.shared.b16 {%0,%1,%2,%3}, [%4];"
                 : "=r"(r[0]), "=r"(r[1]), "=r"(r[2]), "=r"(r[3]) : "r"(addr));
}
__device__ __forceinline__ void mma16816(float* d, const uint32_t* a,
                                         uint32_t b0, uint32_t b1) {
    asm volatile(
        "mma.sync.aligned.m16n8k16.row.col.f32.f16.f16.f32 "
        "{%0,%1,%2,%3}, {%4,%5,%6,%7}, {%8,%9}, {%0,%1,%2,%3};"
        : "+f"(d[0]), "+f"(d[1]), "+f"(d[2]), "+f"(d[3])
        : "r"(a[0]), "r"(a[1]), "r"(a[2]), "r"(a[3]), "r"(b0), "r"(b1));
}

// ---------------------------------------------------------------------------
// Kernel 1 (fused prep): blocks [0,512) pool, blocks [512, 512+4096) transpose.
// Pool: 8 anchors per 256-thread block; per-anchor cell linked lists built
// with smem atomicExch; writeout warp-per-anchor with register accumulation.
// ---------------------------------------------------------------------------
__global__ __launch_bounds__(256) void prep_kernel(
    const float* __restrict__ h_states, const float* __restrict__ end_pos,
    const float* __restrict__ W)
{
    extern __shared__ __align__(16) char sm[];
    const int tid = threadIdx.x;

    if (blockIdx.x < POOL_BLOCKS) {
        float*  sh_hidden = (float*)sm;                 // 4096 f32
        float2* sh_pos    = (float2*)(sm + PK_POS);     // 64
        int*    sh_head   = (int*)(sm + PK_HEAD);       // [PA][64]
        int*    sh_next   = (int*)(sm + PK_NEXT);       // [PA][64]

        const int blk = blockIdx.x;
        const int s  = blk >> 3;            // 8 blocks per sequence
        const int a0 = (blk & 7) * PA;      // first anchor

        const float4* hseq = (const float4*)(h_states + (size_t)s * PP * H_DIM);
        #pragma unroll
        for (int k = tid; k < PP * H_DIM / 4; k += 256)
            ((float4*)sh_hidden)[k] = hseq[k];
        if (tid < PP) sh_pos[tid] = ((const float2*)end_pos)[(size_t)s * PP + tid];
        #pragma unroll
        for (int k = tid; k < PA * 64; k += 256) sh_head[k] = -1;
        __syncthreads();

        // build per-anchor cell lists: idx = (anchor a, neighbor j)
        #pragma unroll
        for (int idx = tid; idx < PA * 64; idx += 256) {
            int a = idx >> 6, j = idx & 63;
            int p = a0 + a;
            float px = sh_pos[p].x, py = sh_pos[p].y;
            float tlx = px - 1.0f, tly = py + 1.0f;
            float brx = px + 1.0f, bry = py - 1.0f;
            float ox = sh_pos[j].x, oy = sh_pos[j].y;
            bool oob = (ox >= brx) || (ox <= tlx) || (oy >= tly) || (oy <= bry) || (j == p);
            int cx = (int)floorf((ox - tlx) / 2.0f * 8.0f);
            int cy = (int)floorf((tly - oy) / 2.0f * 8.0f);
            int c = cx + cy * 8;
            if (!oob && c >= 0 && c < G2)
                sh_next[idx] = atomicExch(&sh_head[a * 64 + c], j);
        }
        __syncthreads();

        // writeout: warp w = anchor; lanes hold head[] in regs, chains walked
        // with uniform j (shfl broadcast) -> coalesced 256B hidden reads.
        const int w = tid >> 5, l = tid & 31;
        const int h0 = sh_head[w * 64 + l];
        const int h1 = sh_head[w * 64 + 32 + l];
        const int* nx = sh_next + w * 64;
        const float2* hid2 = (const float2*)sh_hidden;
        uint32_t* dst = (uint32_t*)(g_poolh + (size_t)(s * PP + a0 + w) * (G2 * H_DIM));
        #pragma unroll
        for (int c = 0; c < G2; c++) {
            int j = __shfl_sync(0xffffffffu, (c < 32) ? h0 : h1, c & 31);
            uint32_t u = 0u;
            if (j >= 0) {                        // warp-uniform branch
                float2 acc = hid2[j * 32 + l];
                j = nx[j];
                while (j >= 0) {                 // warp-uniform chain (rare >1)
                    float2 v = hid2[j * 32 + l];
                    acc.x += v.x; acc.y += v.y;
                    j = nx[j];
                }
                __half2 h = __floats2half2_rn(acc.x, acc.y);
                u = *reinterpret_cast<uint32_t*>(&h);
            }
            dst[c * 32 + l] = u;
        }
    } else {
        // W[K,N] fp32 -> Wt[N,K] fp16, 32x32 tiles
        float (*tile)[33] = (float(*)[33])sm;
        const int bid = blockIdx.x - POOL_BLOCKS;
        const int n0 = (bid & 31) * 32, k0 = (bid >> 5) * 32;
        const int tx = tid & 31, ty = tid >> 5;   // (32, 8)
        #pragma unroll
        for (int i = 0; i < 4; i++) {
            int r = ty + i * 8;
            tile[r][tx] = W[(size_t)(k0 + r) * N_TOT + n0 + tx];
        }
        __syncthreads();
        #pragma unroll
        for (int i = 0; i < 4; i++) {
            int r = ty + i * 8;
            g_Wth[(size_t)(n0 + r) * K_TOT + k0 + tx] = __float2half_rn(tile[tx][r]);
        }
    }
}

// ---------------------------------------------------------------------------
// Kernel 2: C = relu(A @ W + bias), fp16 mma m16n8k16, f32 accumulate.
// 128 threads = 4 warps as 2(M) x 2(N), warp tile 64x64. 4-stage cp.async.
// ---------------------------------------------------------------------------
__global__ __launch_bounds__(128, 2) void gemm_hmma(
    const float* __restrict__ bias, float* __restrict__ C)
{
    extern __shared__ __align__(16) __half smem[];

    const int tid = threadIdx.x;
    const int wid = tid >> 5, lane = tid & 31;
    const int g = lane >> 2, tig = lane & 3;
    const int warp_m = wid & 1, warp_n = wid >> 1;
    const int bm0 = blockIdx.y * BM, bn0 = blockIdx.x * BN;

    float acc[4][8][4];
    #pragma unroll
    for (int mt = 0; mt < 4; mt++)
        #pragma unroll
        for (int nt = 0; nt < 8; nt++)
            #pragma unroll
            for (int r = 0; r < 4; r++) acc[mt][nt][r] = 0.0f;

    const uint32_t sbase = smem_u32(smem);

    auto load_stage = [&](int st, int c) {
        const int k0 = c * BKF;
        uint32_t sa = sbase + (uint32_t)(st * STAGE_BYTES);
        uint32_t sb = sa + A_BYTES;
        #pragma unroll
        for (int i = 0; i < 4; i++) {
            int idx = tid + i * 128;
            int row = idx >> 2, v = idx & 3;
            cp16(sa + (uint32_t)(row * (LDAH * 2) + v * 16),
                 g_poolh + (size_t)(bm0 + row) * K_TOT + k0 + v * 8);
        }
        #pragma unroll
        for (int i = 0; i < 4; i++) {
            int idx = tid + i * 128;
            int row = idx >> 2, v = idx & 3;
            cp16(sb + (uint32_t)(row * (LDAH * 2) + v * 16),
                 g_Wth + (size_t)(bn0 + row) * K_TOT + k0 + v * 8);
        }
        cp_commit();
    };

    load_stage(0, 0);
    load_stage(1, 1);
    load_stage(2, 2);

    const int q = lane >> 3, r8 = lane & 7;

    for (int c = 0; c < NC; c++) {
        cp_wait<2>();
        __syncthreads();

        if (c + 3 < NC) load_stage((c + 3) % NST, c + 3);

        uint32_t sa = sbase + (uint32_t)((c % NST) * STAGE_BYTES);
        uint32_t sb = sa + A_BYTES;

        #pragma unroll
        for (int ks = 0; ks < 2; ks++) {
            const int k0 = ks * 16;
            uint32_t a[4][4], b[4][4];
            #pragma unroll
            for (int mt = 0; mt < 4; mt++) {
                int row = warp_m * 64 + mt * 16 + (q & 1) * 8 + r8;
                int col = k0 + (q >> 1) * 8;
                ldsm4(a[mt], sa + (uint32_t)(row * (LDAH * 2) + col * 2));
            }
            #pragma unroll
            for (int nb = 0; nb < 4; nb++) {
                int row = warp_n * 64 + nb * 16 + (q >> 1) * 8 + r8;
                int col = k0 + (q & 1) * 8;
                ldsm4(b[nb], sb + (uint32_t)(row * (LDAH * 2) + col * 2));
            }
            #pragma unroll
            for (int mt = 0; mt < 4; mt++)
                #pragma unroll
                for (int nb = 0; nb < 4; nb++) {
                    mma16816(acc[mt][2 * nb],     a[mt], b[nb][0], b[nb][1]);
                    mma16816(acc[mt][2 * nb + 1], a[mt], b[nb][2], b[nb][3]);
                }
        }
    }

    // epilogue: bias hoisted, relu, float2 stores
    float2 bb[8];
    #pragma unroll
    for (int nt = 0; nt < 8; nt++) {
        int col = bn0 + warp_n * 64 + nt * 8 + tig * 2;
        bb[nt].x = __ldg(bias + col);
        bb[nt].y = __ldg(bias + col + 1);
    }
    #pragma unroll
    for (int mt = 0; mt < 4; mt++) {
        int r0 = bm0 + warp_m * 64 + mt * 16 + g;
        #pragma unroll
        for (int nt = 0; nt < 8; nt++) {
            int col = bn0 + warp_n * 64 + nt * 8 + tig * 2;
            float2 v0, v1;
            v0.x = fmaxf(acc[mt][nt][0] + bb[nt].x, 0.0f);
            v0.y = fmaxf(acc[mt][nt][1] + bb[nt].y, 0.0f);
            v1.x = fmaxf(acc[mt][nt][2] + bb[nt].x, 0.0f);
            v1.y = fmaxf(acc[mt][nt][3] + bb[nt].y, 0.0f);
            *(float2*)(C + (size_t)r0 * N_TOT + col) = v0;
            *(float2*)(C + (size_t)(r0 + 8) * N_TOT + col) = v1;
        }
    }
}

// ---------------------------------------------------------------------------
// Launch
// ---------------------------------------------------------------------------
extern "C" void kernel_launch(void* const* d_in, const int* in_sizes, int n_in,
                              void* d_out, int out_size)
{
    const float* h_states = (const float*)d_in[0];
    const float* end_pos  = (const float*)d_in[2];
    const float* W        = (const float*)d_in[4];
    const float* bias     = (const float*)d_in[5];
    float* out = (float*)d_out;

    static int attr_set = 0;
    if (!attr_set) {
        cudaFuncSetAttribute(gemm_hmma, cudaFuncAttributeMaxDynamicSharedMemorySize,
                             SMEM_GEMM);
        cudaFuncSetAttribute(prep_kernel, cudaFuncAttributeMaxDynamicSharedMemorySize,
                             SMEM_PREP);
        attr_set = 1;
    }

    int tr_blocks = (N_TOT / 32) * (K_TOT / 32);   // 4096
    prep_kernel<<<POOL_BLOCKS + tr_blocks, 256, SMEM_PREP>>>(h_states, end_pos, W);
    gemm_hmma<<<dim3(N_TOT / BN, M_TOT / BM), 128, SMEM_GEMM>>>(bias, out);
}